// round 16
// baseline (speedup 1.0000x reference)
#include <cuda_runtime.h>

#define TT 128
#define BB 512
#define QQ 50
#define BQ (BB * QQ)                 // 25600
#define GAMMA_F 0.99f
#define NCHT 13                      // 13 chunks/tiles of 10 t-rows
#define TH 10
#define UNITS 10
#define RST 52                       // smem row stride, 16B aligned

// Per-chunk affine composites: ret[10c] = A * ret[hi_c + 1] + B, per chain n.
__device__ float2 g_AB[NCHT * BQ];

// ---------------------------------------------------------------------------
// Kernel 1: chunk composites (tiny; L2-hot output).
// ---------------------------------------------------------------------------
__global__ __launch_bounds__(128)
void k_scan(const float* __restrict__ reward,
            const int*   __restrict__ step_type,
            const float* __restrict__ discount,
            const float* __restrict__ tvalue,
            float*       __restrict__ out)
{
    const int n = blockIdx.x * 128 + threadIdx.x;   // chain 0..25599
    const int c = blockIdx.y;                        // chunk 0..12
    if (c == 0 && n < BB) out[(TT - 1) * BB + n] = 0.0f;   // poisoned row
    const int b  = n / QQ;
    const int lo = TH * c;
    const int hi = min(lo + TH - 1, TT - 2);

    float A = 1.0f, Bv = 0.0f;
    #pragma unroll
    for (int k = 0; k < TH; ++k) {
        const int t = hi - k;
        if (t >= lo) {
            float tv = tvalue[t * BQ + n];
            int   il = step_type[t * BB + b];
            float r  = reward[(t + 1) * BB + b];
            float d  = discount[(t + 1) * BB + b] * GAMMA_F;
            float a  = (il == 2) ? 0.0f : d;
            A  = a * A;
            Bv = fmaf(a, Bv, (il == 2) ? tv : r);
        }
    }
    g_AB[c * BQ + n] = make_float2(A, Bv);
}

// ---------------------------------------------------------------------------
// Kernel 2: self-seeding pairs block = (b, 10-row tile).
//   stage tvalue rows -> seed from <=12 L2-hot composites -> 10-step walk
//   -> frozen one-item-per-thread pair phase.
// ---------------------------------------------------------------------------

#define PAIR2(r2_, nv2_, S2_, D2_) do {                                        \
    unsigned long long x2_, c2_, m2_, t2_;                                     \
    asm("add.rn.f32x2 %0, %1, %2;" : "=l"(x2_) : "l"(r2_), "l"(nv2_));         \
    float xl_, xh_;                                                            \
    asm("mov.b64 {%0, %1}, %2;" : "=f"(xl_), "=f"(xh_) : "l"(x2_));            \
    float ml_ = fminf(fabsf(xl_), 1.0f);                                       \
    float mh_ = fminf(fabsf(xh_), 1.0f);                                       \
    float cl_ = __int_as_float((__float_as_int(xl_) & 0x80000000) |            \
                               __float_as_int(ml_));                           \
    float ch_ = __int_as_float((__float_as_int(xh_) & 0x80000000) |            \
                               __float_as_int(mh_));                           \
    asm("mov.b64 %0, {%1, %2};" : "=l"(c2_) : "f"(cl_), "f"(ch_));             \
    asm("mov.b64 %0, {%1, %2};" : "=l"(m2_) : "f"(ml_), "f"(mh_));             \
    asm("fma.rn.f32x2 %0, %1, %2, %3;" : "=l"(t2_)                             \
        : "l"(c2_), "l"(MH2), "l"(x2_));                                       \
    asm("fma.rn.f32x2 %0, %1, %2, %0;" : "+l"(S2_) : "l"(c2_), "l"(t2_));      \
    asm("fma.rn.f32x2 %0, %1, %2, %0;" : "+l"(D2_) : "l"(m2_), "l"(t2_));      \
} while (0)

__global__ __launch_bounds__(256, 6)
void k_tile(const float* __restrict__ reward,
            const int*   __restrict__ step_type,
            const float* __restrict__ discount,
            const float* __restrict__ value,
            const float* __restrict__ tvalue,
            float*       __restrict__ out)
{
    __shared__ __align__(16) float s_ret[UNITS][RST];
    __shared__ float s_part[UNITS][QQ];
    __shared__ float s_a[UNITS], s_r[UNITS];
    __shared__ int   s_il[UNITS];

    const int tid = threadIdx.x;
    const int b   = blockIdx.x;
    const int c   = blockIdx.y;                      // tile 0..12
    const int lo  = TH * c;
    const int hi  = min(lo + TH - 1, TT - 2);
    const int nu  = hi - lo + 1;                     // 10 (7 for c=12)

    const int u  = tid / 25;
    const int jp = tid - u * 25;

    // ---- Stage this tile's tvalue rows into s_ret ----
    if (tid < UNITS * 25 && u < nu)
        ((float2*)&s_ret[u][0])[jp] =
            *(const float2*)&tvalue[(lo + u) * BQ + b * QQ + 2 * jp];
    // Per-t scalars
    if (tid < nu) {
        const int t  = lo + tid;
        const int il = step_type[t * BB + b];
        s_il[tid] = il;
        s_r[tid]  = reward[(t + 1) * BB + b];
        s_a[tid]  = (il == 2) ? 0.0f
                              : discount[(t + 1) * BB + b] * GAMMA_F;
    }

    // ---- Prefetch pair-phase value operands (independent of walk) ----
    float2 v2 = make_float2(0.0f, 0.0f);
    if (tid < UNITS * 25 && u < nu)
        v2 = *(const float2*)&value[(lo + u) * BQ + b * QQ + 2 * jp];

    // ---- Seed: ret[hi+1] from tvalue[127] + L2-hot chunk composites ----
    float carry = 0.0f;
    if (tid < QQ) {
        carry = tvalue[(TT - 1) * BQ + b * QQ + tid];   // ret[127]
        float2 ab[6];
        #pragma unroll
        for (int i = 0; i < 6; ++i) {                   // chunks 12..7
            const int cc = 12 - i;
            if (cc > c) ab[i] = g_AB[cc * BQ + b * QQ + tid];
        }
        #pragma unroll
        for (int i = 0; i < 6; ++i) {
            const int cc = 12 - i;
            if (cc > c) carry = fmaf(ab[i].x, carry, ab[i].y);
        }
        #pragma unroll
        for (int i = 0; i < 6; ++i) {                   // chunks 6..1
            const int cc = 6 - i;
            if (cc > c) ab[i] = g_AB[cc * BQ + b * QQ + tid];
        }
        #pragma unroll
        for (int i = 0; i < 6; ++i) {
            const int cc = 6 - i;
            if (cc > c) carry = fmaf(ab[i].x, carry, ab[i].y);
        }
        // carry == ret[hi+1]
    }
    __syncthreads();

    // ---- 10-step walk in registers; results overwrite s_ret ----
    if (tid < QQ) {
        float tv[TH];
        #pragma unroll
        for (int k = 0; k < TH; ++k)
            if (k < nu) tv[k] = s_ret[k][tid];
        #pragma unroll
        for (int k = TH - 1; k >= 0; --k) {
            if (k < nu) {
                float bb2 = (s_il[k] == 2) ? tv[k] : s_r[k];
                carry = fmaf(s_a[k], carry, bb2);
                s_ret[k][tid] = carry;
            }
        }
    }
    __syncthreads();

    // ---- Frozen pair phase: one (u, j-pair) item per thread ----
    if (tid < UNITS * 25 && u < nu) {
        unsigned long long nv2a, nv2b;
        {
            float na = -v2.x, nb = -v2.y;
            asm("mov.b64 %0, {%1, %1};" : "=l"(nv2a) : "f"(na));
            asm("mov.b64 %0, {%1, %1};" : "=l"(nv2b) : "f"(nb));
        }
        const unsigned long long MH2 = 0xBF000000BF000000ULL;   // (-0.5,-0.5)
        unsigned long long S2a = 0, D2a = 0, S2b = 0, D2b = 0;

        const ulonglong2* rp2 = (const ulonglong2*)&s_ret[u][0];
        #pragma unroll
        for (int p = 0; p < 12; ++p) {               // 48 returns via LDS.128
            ulonglong2 rr = rp2[p];
            PAIR2(rr.x, nv2a, S2a, D2a);
            PAIR2(rr.x, nv2b, S2b, D2b);
            PAIR2(rr.y, nv2a, S2a, D2a);
            PAIR2(rr.y, nv2b, S2b, D2b);
        }
        {                                            // returns 48, 49
            unsigned long long rt_ = *(const unsigned long long*)&s_ret[u][48];
            PAIR2(rt_, nv2a, S2a, D2a);
            PAIR2(rt_, nv2b, S2b, D2b);
        }

        float sl, sh, dl, dh;
        asm("mov.b64 {%0, %1}, %2;" : "=f"(sl), "=f"(sh) : "l"(S2a));
        asm("mov.b64 {%0, %1}, %2;" : "=f"(dl), "=f"(dh) : "l"(D2a));
        const float taua = (2 * jp + 0.5f) * (1.0f / QQ);
        s_part[u][2 * jp]     = fmaf(taua - 0.5f, dl + dh, 0.5f * (sl + sh));

        asm("mov.b64 {%0, %1}, %2;" : "=f"(sl), "=f"(sh) : "l"(S2b));
        asm("mov.b64 {%0, %1}, %2;" : "=f"(dl), "=f"(dh) : "l"(D2b));
        const float taub = (2 * jp + 1.5f) * (1.0f / QQ);
        s_part[u][2 * jp + 1] = fmaf(taub - 0.5f, dl + dh, 0.5f * (sl + sh));
    }
    __syncthreads();

    // ---- Deterministic fixed-order j-reduction ----
    if (tid < nu) {
        float s = 0.0f;
        #pragma unroll
        for (int j = 0; j < QQ; ++j) s += s_part[tid][j];
        out[(lo + tid) * BB + b] = s * (1.0f / QQ);
    }
}

extern "C" void kernel_launch(void* const* d_in, const int* in_sizes, int n_in,
                              void* d_out, int out_size)
{
    const float* reward    = (const float*)d_in[0];
    const int*   step_type = (const int*)  d_in[1];
    const float* discount  = (const float*)d_in[2];
    const float* value     = (const float*)d_in[3];
    const float* tvalue    = (const float*)d_in[4];
    float*       out       = (float*)d_out;

    dim3 gs(BQ / 128, NCHT);                         // (200, 13)
    k_scan<<<gs, 128>>>(reward, step_type, discount, tvalue, out);

    dim3 gt(BB, NCHT);                               // 6656 blocks
    k_tile<<<gt, 256>>>(reward, step_type, discount, value, tvalue, out);
}

// round 17
// speedup vs baseline: 1.0519x; 1.0519x over previous
#include <cuda_runtime.h>

#define TT 128
#define BB 512
#define QQ 50
#define BQ (BB * QQ)                 // 25600
#define GAMMA_F 0.99f
#define NCHT 13                      // 13 chunks/tiles of 10 t-rows
#define TH 10
#define UNITS 10
#define RST 52                       // smem row stride, 16B aligned

// Per-chunk affine composites: ret[10c] = A * ret[hi_c + 1] + B, per chain n.
__device__ float2 g_AB[NCHT * BQ];

// ---------------------------------------------------------------------------
// Kernel 1: chunk composites (tiny; L2-hot output).
// ---------------------------------------------------------------------------
__global__ __launch_bounds__(128)
void k_scan(const float* __restrict__ reward,
            const int*   __restrict__ step_type,
            const float* __restrict__ discount,
            const float* __restrict__ tvalue,
            float*       __restrict__ out)
{
    const int n = blockIdx.x * 128 + threadIdx.x;   // chain 0..25599
    const int c = blockIdx.y;                        // chunk 0..12
    if (c == 0 && n < BB) out[(TT - 1) * BB + n] = 0.0f;   // poisoned row
    const int b  = n / QQ;
    const int lo = TH * c;
    const int hi = min(lo + TH - 1, TT - 2);

    float A = 1.0f, Bv = 0.0f;
    #pragma unroll
    for (int k = 0; k < TH; ++k) {
        const int t = hi - k;
        if (t >= lo) {
            float tv = tvalue[t * BQ + n];
            int   il = step_type[t * BB + b];
            float r  = reward[(t + 1) * BB + b];
            float d  = discount[(t + 1) * BB + b] * GAMMA_F;
            float a  = (il == 2) ? 0.0f : d;
            A  = a * A;
            Bv = fmaf(a, Bv, (il == 2) ? tv : r);
        }
    }
    g_AB[c * BQ + n] = make_float2(A, Bv);
}

// ---------------------------------------------------------------------------
// Kernel 2: self-seeding pairs block = (b, 10-row tile).
//   stage tvalue rows -> seed from <=12 L2-hot composites -> 10-step walk
//   -> frozen one-item-per-thread pair phase.
// ---------------------------------------------------------------------------

#define PAIR2(r2_, nv2_, S2_, D2_) do {                                        \
    unsigned long long x2_, c2_, m2_, t2_;                                     \
    asm("add.rn.f32x2 %0, %1, %2;" : "=l"(x2_) : "l"(r2_), "l"(nv2_));         \
    float xl_, xh_;                                                            \
    asm("mov.b64 {%0, %1}, %2;" : "=f"(xl_), "=f"(xh_) : "l"(x2_));            \
    float ml_ = fminf(fabsf(xl_), 1.0f);                                       \
    float mh_ = fminf(fabsf(xh_), 1.0f);                                       \
    float cl_ = __int_as_float((__float_as_int(xl_) & 0x80000000) |            \
                               __float_as_int(ml_));                           \
    float ch_ = __int_as_float((__float_as_int(xh_) & 0x80000000) |            \
                               __float_as_int(mh_));                           \
    asm("mov.b64 %0, {%1, %2};" : "=l"(c2_) : "f"(cl_), "f"(ch_));             \
    asm("mov.b64 %0, {%1, %2};" : "=l"(m2_) : "f"(ml_), "f"(mh_));             \
    asm("fma.rn.f32x2 %0, %1, %2, %3;" : "=l"(t2_)                             \
        : "l"(c2_), "l"(MH2), "l"(x2_));                                       \
    asm("fma.rn.f32x2 %0, %1, %2, %0;" : "+l"(S2_) : "l"(c2_), "l"(t2_));      \
    asm("fma.rn.f32x2 %0, %1, %2, %0;" : "+l"(D2_) : "l"(m2_), "l"(t2_));      \
} while (0)

__global__ __launch_bounds__(256, 6)
void k_tile(const float* __restrict__ reward,
            const int*   __restrict__ step_type,
            const float* __restrict__ discount,
            const float* __restrict__ value,
            const float* __restrict__ tvalue,
            float*       __restrict__ out)
{
    __shared__ __align__(16) float s_ret[UNITS][RST];
    __shared__ float s_part[UNITS][QQ];
    __shared__ float s_a[UNITS], s_r[UNITS];
    __shared__ int   s_il[UNITS];

    const int tid = threadIdx.x;
    const int b   = blockIdx.x;
    const int c   = blockIdx.y;                      // tile 0..12
    const int lo  = TH * c;
    const int hi  = min(lo + TH - 1, TT - 2);
    const int nu  = hi - lo + 1;                     // 10 (7 for c=12)

    const int u  = tid / 25;
    const int jp = tid - u * 25;

    // ---- Stage this tile's tvalue rows into s_ret ----
    if (tid < UNITS * 25 && u < nu)
        ((float2*)&s_ret[u][0])[jp] =
            *(const float2*)&tvalue[(lo + u) * BQ + b * QQ + 2 * jp];
    // Per-t scalars
    if (tid < nu) {
        const int t  = lo + tid;
        const int il = step_type[t * BB + b];
        s_il[tid] = il;
        s_r[tid]  = reward[(t + 1) * BB + b];
        s_a[tid]  = (il == 2) ? 0.0f
                              : discount[(t + 1) * BB + b] * GAMMA_F;
    }

    // ---- Prefetch pair-phase value operands (independent of walk) ----
    float2 v2 = make_float2(0.0f, 0.0f);
    if (tid < UNITS * 25 && u < nu)
        v2 = *(const float2*)&value[(lo + u) * BQ + b * QQ + 2 * jp];

    // ---- Seed: ret[hi+1] from tvalue[127] + L2-hot chunk composites ----
    float carry = 0.0f;
    if (tid < QQ) {
        carry = tvalue[(TT - 1) * BQ + b * QQ + tid];   // ret[127]
        float2 ab[6];
        #pragma unroll
        for (int i = 0; i < 6; ++i) {                   // chunks 12..7
            const int cc = 12 - i;
            if (cc > c) ab[i] = g_AB[cc * BQ + b * QQ + tid];
        }
        #pragma unroll
        for (int i = 0; i < 6; ++i) {
            const int cc = 12 - i;
            if (cc > c) carry = fmaf(ab[i].x, carry, ab[i].y);
        }
        #pragma unroll
        for (int i = 0; i < 6; ++i) {                   // chunks 6..1
            const int cc = 6 - i;
            if (cc > c) ab[i] = g_AB[cc * BQ + b * QQ + tid];
        }
        #pragma unroll
        for (int i = 0; i < 6; ++i) {
            const int cc = 6 - i;
            if (cc > c) carry = fmaf(ab[i].x, carry, ab[i].y);
        }
        // carry == ret[hi+1]
    }
    __syncthreads();

    // ---- 10-step walk in registers; results overwrite s_ret ----
    if (tid < QQ) {
        float tv[TH];
        #pragma unroll
        for (int k = 0; k < TH; ++k)
            if (k < nu) tv[k] = s_ret[k][tid];
        #pragma unroll
        for (int k = TH - 1; k >= 0; --k) {
            if (k < nu) {
                float bb2 = (s_il[k] == 2) ? tv[k] : s_r[k];
                carry = fmaf(s_a[k], carry, bb2);
                s_ret[k][tid] = carry;
            }
        }
    }
    __syncthreads();

    // ---- Frozen pair phase: one (u, j-pair) item per thread ----
    if (tid < UNITS * 25 && u < nu) {
        unsigned long long nv2a, nv2b;
        {
            float na = -v2.x, nb = -v2.y;
            asm("mov.b64 %0, {%1, %1};" : "=l"(nv2a) : "f"(na));
            asm("mov.b64 %0, {%1, %1};" : "=l"(nv2b) : "f"(nb));
        }
        const unsigned long long MH2 = 0xBF000000BF000000ULL;   // (-0.5,-0.5)
        unsigned long long S2a = 0, D2a = 0, S2b = 0, D2b = 0;

        const ulonglong2* rp2 = (const ulonglong2*)&s_ret[u][0];
        #pragma unroll
        for (int p = 0; p < 12; ++p) {               // 48 returns via LDS.128
            ulonglong2 rr = rp2[p];
            PAIR2(rr.x, nv2a, S2a, D2a);
            PAIR2(rr.x, nv2b, S2b, D2b);
            PAIR2(rr.y, nv2a, S2a, D2a);
            PAIR2(rr.y, nv2b, S2b, D2b);
        }
        {                                            // returns 48, 49
            unsigned long long rt_ = *(const unsigned long long*)&s_ret[u][48];
            PAIR2(rt_, nv2a, S2a, D2a);
            PAIR2(rt_, nv2b, S2b, D2b);
        }

        float sl, sh, dl, dh;
        asm("mov.b64 {%0, %1}, %2;" : "=f"(sl), "=f"(sh) : "l"(S2a));
        asm("mov.b64 {%0, %1}, %2;" : "=f"(dl), "=f"(dh) : "l"(D2a));
        const float taua = (2 * jp + 0.5f) * (1.0f / QQ);
        s_part[u][2 * jp]     = fmaf(taua - 0.5f, dl + dh, 0.5f * (sl + sh));

        asm("mov.b64 {%0, %1}, %2;" : "=f"(sl), "=f"(sh) : "l"(S2b));
        asm("mov.b64 {%0, %1}, %2;" : "=f"(dl), "=f"(dh) : "l"(D2b));
        const float taub = (2 * jp + 1.5f) * (1.0f / QQ);
        s_part[u][2 * jp + 1] = fmaf(taub - 0.5f, dl + dh, 0.5f * (sl + sh));
    }
    __syncthreads();

    // ---- Deterministic fixed-order j-reduction ----
    if (tid < nu) {
        float s = 0.0f;
        #pragma unroll
        for (int j = 0; j < QQ; ++j) s += s_part[tid][j];
        out[(lo + tid) * BB + b] = s * (1.0f / QQ);
    }
}

extern "C" void kernel_launch(void* const* d_in, const int* in_sizes, int n_in,
                              void* d_out, int out_size)
{
    const float* reward    = (const float*)d_in[0];
    const int*   step_type = (const int*)  d_in[1];
    const float* discount  = (const float*)d_in[2];
    const float* value     = (const float*)d_in[3];
    const float* tvalue    = (const float*)d_in[4];
    float*       out       = (float*)d_out;

    dim3 gs(BQ / 128, NCHT);                         // (200, 13)
    k_scan<<<gs, 128>>>(reward, step_type, discount, tvalue, out);

    dim3 gt(BB, NCHT);                               // 6656 blocks
    k_tile<<<gt, 256>>>(reward, step_type, discount, value, tvalue, out);
}